// round 11
// baseline (speedup 1.0000x reference)
#include <cuda_runtime.h>
#include <cuda_fp16.h>
#include <cstdint>

#define B_TOTAL  8192
#define T_STEPS  512
#define HID      128
#define BM       64      // rows per CTA = 4 warps x 16-row M-tiles
#define NTHREADS 128
#define NKT      9       // k-tiles: 128 h + [x0,x1,bias,0..] tile
#define NNT      16      // n-tiles: N = 128
#define ALPHA_C  0.2f
#define BETA_C   0.7f

// B fragments: one uint4 per (nt,kt,lane) = {term0.b0, term0.b1, term1.b0, term1.b1}
#define SB_BYTES (NKT * NNT * 32 * 16)   // 73728

__device__ __forceinline__ float tanh_hw(float x) {
    float y; asm("tanh.approx.f32 %0, %1;" : "=f"(y) : "f"(x)); return y;
}
// pack {lo, hi} floats -> f16x2 register
__device__ __forceinline__ uint32_t f16x2(float lo, float hi) {
    uint32_t r; asm("cvt.rn.f16x2.f32 %0, %1, %2;" : "=r"(r) : "f"(hi), "f"(lo));
    return r;
}
// m16n8k16 f16 HMMA, accumulate in place
__device__ __forceinline__ void mma16816(float c[4], const uint32_t a[4],
                                         uint32_t b0, uint32_t b1) {
    asm("mma.sync.aligned.m16n8k16.row.col.f32.f16.f16.f32 "
        "{%0,%1,%2,%3}, {%4,%5,%6,%7}, {%8,%9}, {%0,%1,%2,%3};"
        : "+f"(c[0]), "+f"(c[1]), "+f"(c[2]), "+f"(c[3])
        : "r"(a[0]), "r"(a[1]), "r"(a[2]), "r"(a[3]), "r"(b0), "r"(b1));
}

extern __shared__ char smem[];

__global__ __launch_bounds__(NTHREADS, 1)
void rnn_kernel(const float* __restrict__ input,   // (B, T, 2)
                const float* __restrict__ W_rec,   // (130, 128)
                const float* __restrict__ b_rec,   // (128)
                const float* __restrict__ W_out,   // (128, 1)
                const float* __restrict__ b_out,   // (1)
                float* __restrict__ out)           // (B)
{
    uint4*  sB  = (uint4*)smem;                    // [nt][kt][lane]
    float2* sWP = (float2*)(smem + SB_BYTES);      // [nt][tig] wout col pairs

    const int tid  = threadIdx.x;
    const int lane = tid & 31;
    const int wid  = tid >> 5;
    const int tig  = lane & 3;     // col group within fragment
    const int gid  = lane >> 2;    // row group 0..7
    const int bBase = blockIdx.x * BM;

    // ---- build B fragments: W'(k,n) split into f16 hi (term0) + residual (term1)
    // W'(k,n): k<128 -> W_rec[k+2][n]; 128->W_rec[0][n]; 129->W_rec[1][n];
    //          130 -> b_rec[n]; else 0.
    for (int idx = tid; idx < NKT * NNT * 32; idx += NTHREADS) {
        int l  = idx & 31;
        int kt = (idx >> 5) % NKT;
        int nt = (idx >> 5) / NKT;
        int n  = nt * 8 + (l >> 2);
        int kb = kt * 16 + 2 * (l & 3);
        unsigned short h0q[4], h1q[4];
        #pragma unroll
        for (int q = 0; q < 4; q++) {
            int k = kb + (q >> 1) * 8 + (q & 1);
            float v;
            if      (k < 128)  v = W_rec[(k + 2) * HID + n];
            else if (k == 128) v = W_rec[n];
            else if (k == 129) v = W_rec[HID + n];
            else if (k == 130) v = b_rec[n];
            else               v = 0.0f;
            __half vh = __float2half_rn(v);
            __half vl = __float2half_rn(v - __half2float(vh));
            h0q[q] = __half_as_ushort(vh);
            h1q[q] = __half_as_ushort(vl);
        }
        uint4 bv;
        bv.x = (uint32_t)h0q[0] | ((uint32_t)h0q[1] << 16);
        bv.y = (uint32_t)h0q[2] | ((uint32_t)h0q[3] << 16);
        bv.z = (uint32_t)h1q[0] | ((uint32_t)h1q[1] << 16);
        bv.w = (uint32_t)h1q[2] | ((uint32_t)h1q[3] << 16);
        sB[(nt * NKT + kt) * 32 + l] = bv;
    }
    if (tid < NNT * 4) {
        int nt = tid >> 2, c = tid & 3;
        sWP[tid] = make_float2(W_out[nt * 8 + 2 * c], W_out[nt * 8 + 2 * c + 1]);
    }
    __syncthreads();

    // ---- per-thread recurrent state ----
    const int r0 = wid * 16 + gid;     // local rows r0 and r0+8
    const int r8 = r0 + 8;
    const long long off0 = (long long)(bBase + r0) * (T_STEPS * 2);
    const long long off8 = (long long)(bBase + r8) * (T_STEPS * 2);
    const float bout = b_out[0];

    float2 x0c = *(const float2*)(input + off0);   // x_0
    float2 x8c = *(const float2*)(input + off8);
    float racc0 = 0.f, racc8 = 0.f, prev0 = 0.f, prev8 = 0.f;
    float oacc0 = 0.f, oacc8 = 0.f;

    const uint32_t ONEH = 0x00003C00u;   // {lo=1.0h (bias slot), hi=0}

    uint32_t a[NKT][4];
    #pragma unroll
    for (int kt = 0; kt < 8; kt++)
        #pragma unroll
        for (int q = 0; q < 4; q++) a[kt][q] = 0u;   // h_{-1} = 0
    a[8][0] = (tig == 0) ? f16x2(x0c.x, x0c.y) : (tig == 1) ? ONEH : 0u;
    a[8][1] = (tig == 0) ? f16x2(x8c.x, x8c.y) : (tig == 1) ? ONEH : 0u;
    a[8][2] = 0u; a[8][3] = 0u;

    for (int t = 0; t < T_STEPS; ++t) {
        float2 x0n = make_float2(0.f, 0.f), x8n = make_float2(0.f, 0.f);
        if (t + 1 < T_STEPS) {
            x0n = *(const float2*)(input + off0 + (long long)(t + 1) * 2);
            x8n = *(const float2*)(input + off8 + (long long)(t + 1) * 2);
        }

        // GEMM nt-outer: each n-tile's tanh/omega issues while the next
        // n-tile's HMMAs occupy the tensor pipe.
        float c[NNT][4];
        float pr0 = 0.f, pr8 = 0.f;
        #pragma unroll
        for (int nt = 0; nt < NNT; nt++) {
            c[nt][0] = 0.f; c[nt][1] = 0.f; c[nt][2] = 0.f; c[nt][3] = 0.f;
            const uint4* bp = sB + nt * (NKT * 32) + lane;
            #pragma unroll
            for (int kt = 0; kt < NKT; kt++) {
                uint4 bv = bp[kt * 32];
                mma16816(c[nt], a[kt], bv.x, bv.y);   // W hi term
                mma16816(c[nt], a[kt], bv.z, bv.w);   // W residual term
            }
            // epilogue for this n-tile (MUFU/FMA pipes, overlaps next nt's MMAs)
            c[nt][0] = tanh_hw(c[nt][0]);
            c[nt][1] = tanh_hw(c[nt][1]);
            c[nt][2] = tanh_hw(c[nt][2]);
            c[nt][3] = tanh_hw(c[nt][3]);
            float2 wp = sWP[nt * 4 + tig];
            pr0 += c[nt][0] * wp.x + c[nt][1] * wp.y;
            pr8 += c[nt][2] * wp.x + c[nt][3] * wp.y;
        }

        // repack h (now in c) into next-step A fragments
        #pragma unroll
        for (int nt = 0; nt < NNT; nt++) {
            const int kt = nt >> 1, hh = (nt & 1) << 1;
            a[kt][hh]     = f16x2(c[nt][0], c[nt][1]);
            a[kt][hh + 1] = f16x2(c[nt][2], c[nt][3]);
        }

        oacc0 = oacc0 * BETA_C + pr0;
        oacc8 = oacc8 * BETA_C + pr8;
        racc0 = racc0 * BETA_C + prev0 * prev0;  prev0 = x0c.x;
        racc8 = racc8 * BETA_C + prev8 * prev8;  prev8 = x8c.x;

        a[8][0] = (tig == 0) ? f16x2(x0n.x, x0n.y) : (tig == 1) ? ONEH : 0u;
        a[8][1] = (tig == 0) ? f16x2(x8n.x, x8n.y) : (tig == 1) ? ONEH : 0u;
        x0c = x0n; x8c = x8n;
    }

    // reduce omega across the 4 col-group lanes of each quad
    oacc0 += __shfl_xor_sync(0xffffffffu, oacc0, 1);
    oacc0 += __shfl_xor_sync(0xffffffffu, oacc0, 2);
    oacc8 += __shfl_xor_sync(0xffffffffu, oacc8, 1);
    oacc8 += __shfl_xor_sync(0xffffffffu, oacc8, 2);

    if (tig == 0) {
        const float geo = 1.0f / (1.0f - BETA_C);   // beta^512 underflows
        out[bBase + r0] = racc0 * ALPHA_C + oacc0 + bout * geo;
        out[bBase + r8] = racc8 * ALPHA_C + oacc8 + bout * geo;
    }
}

extern "C" void kernel_launch(void* const* d_in, const int* in_sizes, int n_in,
                              void* d_out, int out_size) {
    const float* input = (const float*)d_in[0];
    const float* W_rec = (const float*)d_in[1];
    const float* b_rec = (const float*)d_in[2];
    const float* W_out = (const float*)d_in[3];
    const float* b_out = (const float*)d_in[4];
    float* out = (float*)d_out;

    const size_t smem_bytes = SB_BYTES + NNT * 4 * sizeof(float2);  // 74240
    cudaFuncSetAttribute(rnn_kernel, cudaFuncAttributeMaxDynamicSharedMemorySize,
                         (int)smem_bytes);

    rnn_kernel<<<B_TOTAL / BM, NTHREADS, smem_bytes>>>(input, W_rec, b_rec,
                                                       W_out, b_out, out);
    (void)in_sizes; (void)n_in; (void)out_size;
}